// round 7
// baseline (speedup 1.0000x reference)
#include <cuda_runtime.h>
#include <cuda_fp16.h>
#include <math.h>

#define HID   128
#define HEADS 4
#define HDIM  32
#define NMAX  50176
#define EMAX  800000
#define SCANB 512

// ---------------- scratch ---------------------------------------------------
__device__ __half g_qh[NMAX * HID];
__device__ __half g_kh[NMAX * HID];
__device__ __half g_vh[NMAX * HID];
__device__ __half g_aggh[NMAX * HID];     // normalized attention output (fp16)
__device__ int    g_cnt[NMAX];
__device__ int    g_off[NMAX];
__device__ int    g_cur[NMAX];
__device__ int    g_chunksum[256];
__device__ int2   g_adj[EMAX];            // (col, gate*scale bits) in CSR order

// ---------------- mma helpers -----------------------------------------------
__device__ __forceinline__ unsigned smem_u32(const void* p) {
    return (unsigned)__cvta_generic_to_shared(p);
}
__device__ __forceinline__ void ldsm_x4(unsigned& r0, unsigned& r1,
                                        unsigned& r2, unsigned& r3, unsigned a) {
    asm volatile("ldmatrix.sync.aligned.m8n8.x4.shared.b16 {%0,%1,%2,%3},[%4];"
                 : "=r"(r0), "=r"(r1), "=r"(r2), "=r"(r3) : "r"(a));
}
__device__ __forceinline__ void mma16816(float* c, const unsigned* a, const unsigned* b) {
    asm volatile(
        "mma.sync.aligned.m16n8k16.row.col.f32.f16.f16.f32 "
        "{%0,%1,%2,%3},{%4,%5,%6,%7},{%8,%9},{%0,%1,%2,%3};"
        : "+f"(c[0]), "+f"(c[1]), "+f"(c[2]), "+f"(c[3])
        : "r"(a[0]), "r"(a[1]), "r"(a[2]), "r"(a[3]), "r"(b[0]), "r"(b[1]));
}

#define AKF 136   // full-K padded stride (halves)
#define AK  72    // chunk-K padded stride

// ---------------- zero counts -----------------------------------------------
__global__ void zero_cnt(int n) {
    int i = blockIdx.x * blockDim.x + threadIdx.x;
    if (i < n) g_cnt[i] = 0;
}

// ---------------- fused QKV (single pass, tensor cores) ----------------------
__global__ void __launch_bounds__(256, 2)
qkv_fused(const float* __restrict__ h,
          const float* __restrict__ frac,
          const float* __restrict__ We,
          const float* __restrict__ be,
          const float* __restrict__ Wq, const float* __restrict__ bq,
          const float* __restrict__ Wk, const float* __restrict__ bk,
          const float* __restrict__ Wv, const float* __restrict__ bv,
          int n) {
    extern __shared__ __align__(16) char smem_raw[];
    __half (*As)[AKF] = (__half(*)[AKF])smem_raw;
    __half (*Bs)[AK]  = (__half(*)[AK])(smem_raw + 128 * AKF * 2);
    float (*Fr)[4]  = (float(*)[4])(smem_raw + 128 * AKF * 2 + 128 * AK * 2);
    float (*Wes)[4] = Fr + 128;

    int m0 = blockIdx.x * 128;
    int tid = threadIdx.x;
    int wid = tid >> 5, lane = tid & 31;
    int wm = (wid & 3) * 32;
    int wn = (wid >> 2) * 64;

    if (tid < 128) {
        int kc = tid;
        Wes[kc][0] = We[kc * 3 + 0];
        Wes[kc][1] = We[kc * 3 + 1];
        Wes[kc][2] = We[kc * 3 + 2];
        Wes[kc][3] = be[kc];
        int m = m0 + tid;
        if (m < n) {
            Fr[tid][0] = frac[m * 3 + 0];
            Fr[tid][1] = frac[m * 3 + 1];
            Fr[tid][2] = frac[m * 3 + 2];
        } else {
            Fr[tid][0] = Fr[tid][1] = Fr[tid][2] = 0.f;
        }
    }
    __syncthreads();

    for (int idx = tid; idx < 128 * 32; idx += 256) {
        int r = idx >> 5;
        int k4 = (idx & 31) * 4;
        int m = m0 + r;
        float x[4] = {0.f, 0.f, 0.f, 0.f};
        if (m < n) {
            float4 hv = *(const float4*)&h[m * HID + k4];
            float f0 = Fr[r][0], f1 = Fr[r][1], f2 = Fr[r][2];
            x[0] = hv.x; x[1] = hv.y; x[2] = hv.z; x[3] = hv.w;
#pragma unroll
            for (int u = 0; u < 4; u++) {
                int kc = k4 + u;
                x[u] += f0 * Wes[kc][0] + f1 * Wes[kc][1] + f2 * Wes[kc][2] + Wes[kc][3];
            }
        }
        __half2* dst = (__half2*)&As[r][k4];
        dst[0] = __floats2half2_rn(x[0], x[1]);
        dst[1] = __floats2half2_rn(x[2], x[3]);
    }
    __syncthreads();

    const float* Ws[3] = {Wq, Wk, Wv};
    const float* bs[3] = {bq, bk, bv};
    __half* outs[3]; outs[0] = g_qh; outs[1] = g_kh; outs[2] = g_vh;

    for (int proj = 0; proj < 3; proj++) {
        const float* W = Ws[proj];
        float acc[2][8][4];
#pragma unroll
        for (int i = 0; i < 2; i++)
#pragma unroll
            for (int j = 0; j < 8; j++)
#pragma unroll
                for (int t = 0; t < 4; t++) acc[i][j][t] = 0.f;

        for (int k0 = 0; k0 < HID; k0 += 64) {
            for (int idx = tid; idx < 128 * 16; idx += 256) {
                int c = idx >> 4;
                int k4 = (idx & 15) * 4;
                float4 wv = *(const float4*)&W[c * HID + k0 + k4];
                __half2* dst = (__half2*)&Bs[c][k4];
                dst[0] = __floats2half2_rn(wv.x, wv.y);
                dst[1] = __floats2half2_rn(wv.z, wv.w);
            }
            __syncthreads();
#pragma unroll
            for (int ks = 0; ks < 64; ks += 16) {
                unsigned af[2][4];
#pragma unroll
                for (int mf = 0; mf < 2; mf++) {
                    unsigned a = smem_u32(&As[wm + mf * 16 + (lane & 15)][k0 + ks + (lane >> 4) * 8]);
                    ldsm_x4(af[mf][0], af[mf][1], af[mf][2], af[mf][3], a);
                }
                unsigned bf[8][2];
#pragma unroll
                for (int ng = 0; ng < 4; ng++) {
                    unsigned a = smem_u32(&Bs[wn + ng * 16 + (lane & 15)][ks + (lane >> 4) * 8]);
                    unsigned r0, r1, r2, r3;
                    ldsm_x4(r0, r1, r2, r3, a);
                    bf[ng * 2][0] = r0; bf[ng * 2][1] = r2;
                    bf[ng * 2 + 1][0] = r1; bf[ng * 2 + 1][1] = r3;
                }
#pragma unroll
                for (int mf = 0; mf < 2; mf++)
#pragma unroll
                    for (int nf = 0; nf < 8; nf++)
                        mma16816(acc[mf][nf], af[mf], bf[nf]);
            }
            __syncthreads();
        }

        const float* bias = bs[proj];
        __half* outbuf = outs[proj];
#pragma unroll
        for (int mf = 0; mf < 2; mf++) {
            int r0 = m0 + wm + mf * 16 + (lane >> 2);
#pragma unroll
            for (int nf = 0; nf < 8; nf++) {
                int c = wn + nf * 8 + (lane & 3) * 2;
                float b0 = bias[c], b1 = bias[c + 1];
                if (r0 < n)
                    *(__half2*)&outbuf[r0 * HID + c] =
                        __floats2half2_rn(acc[mf][nf][0] + b0, acc[mf][nf][1] + b1);
                if (r0 + 8 < n)
                    *(__half2*)&outbuf[(r0 + 8) * HID + c] =
                        __floats2half2_rn(acc[mf][nf][2] + b0, acc[mf][nf][3] + b1);
            }
        }
    }
}

// ---------------- degree histogram (thread per edge) -------------------------
__global__ void hist_kernel(const int* __restrict__ ei, int E) {
    int e = blockIdx.x * blockDim.x + threadIdx.x;
    if (e < E) atomicAdd(&g_cnt[ei[e]], 1);
}

// ---------------- 3-phase exclusive scan of g_cnt -> g_off/g_cur -------------
__global__ void scan_phase1(int n) {
    int i = blockIdx.x * SCANB + threadIdx.x;
    int c = (i < n) ? g_cnt[i] : 0;
    for (int o = 16; o; o >>= 1) c += __shfl_down_sync(0xFFFFFFFFu, c, o);
    __shared__ int ws[16];
    if ((threadIdx.x & 31) == 0) ws[threadIdx.x >> 5] = c;
    __syncthreads();
    if (threadIdx.x < 16) {
        int v = ws[threadIdx.x];
        for (int o = 8; o; o >>= 1) v += __shfl_down_sync(0xFFFFu, v, o);
        if (threadIdx.x == 0) g_chunksum[blockIdx.x] = v;
    }
}
__global__ void scan_phase2(int nch) {
    if (threadIdx.x == 0) {
        int run = 0;
        for (int j = 0; j < nch; j++) {
            int t = g_chunksum[j];
            g_chunksum[j] = run;
            run += t;
        }
    }
}
__global__ void scan_phase3(int n) {
    int i = blockIdx.x * SCANB + threadIdx.x;
    int c = (i < n) ? g_cnt[i] : 0;
    int lane = threadIdx.x & 31, w = threadIdx.x >> 5;
    int v = c;
    for (int o = 1; o < 32; o <<= 1) {
        int t = __shfl_up_sync(0xFFFFFFFFu, v, o);
        if (lane >= o) v += t;
    }
    __shared__ int ws[16];
    if (lane == 31) ws[w] = v;
    __syncthreads();
    if (threadIdx.x < 16) {
        int s = ws[threadIdx.x];
        for (int o = 1; o < 16; o <<= 1) {
            int t = __shfl_up_sync(0xFFFFu, s, o);
            if ((int)threadIdx.x >= o) s += t;
        }
        ws[threadIdx.x] = s;
    }
    __syncthreads();
    int base = g_chunksum[blockIdx.x] + (w ? ws[w - 1] : 0);
    int excl = base + v - c;
    if (i < n) { g_off[i] = excl; g_cur[i] = excl; }
}

// ---------------- scatter + fused gate MLP (warp per edge) -------------------
__global__ void scatter_gate(const int* __restrict__ ei,
                             const float* __restrict__ dist,
                             const float* __restrict__ Wg1, const float* __restrict__ bg1,
                             const float* __restrict__ Wg2, const float* __restrict__ bg2,
                             int E) {
    int warp = (blockIdx.x * blockDim.x + threadIdx.x) >> 5;
    int lane = threadIdx.x & 31;
    if (warp >= E) return;

    float d = dist[warp];
    float t = fmaf(d, Wg1[lane], bg1[lane]);
    float hsi = t / (1.f + __expf(-t));
    float gp = hsi * Wg2[lane];
    gp += __shfl_xor_sync(0xFFFFFFFFu, gp, 16);
    gp += __shfl_xor_sync(0xFFFFFFFFu, gp, 8);
    gp += __shfl_xor_sync(0xFFFFFFFFu, gp, 4);
    gp += __shfl_xor_sync(0xFFFFFFFFu, gp, 2);
    gp += __shfl_xor_sync(0xFFFFFFFFu, gp, 1);

    if (lane == 0) {
        float g = 1.f / (1.f + __expf(-(gp + bg2[0])));
        int row = ei[warp];
        int pos = atomicAdd(&g_cur[row], 1);
        g_adj[pos] = make_int2(ei[E + warp],
                               __float_as_int(g * 0.17677669529663687f));
    }
}

// ---------------- pull aggregation: warp per node, unroll x4 -----------------
__global__ void __launch_bounds__(256)
pull_agg(int n) {
    int node = (blockIdx.x * blockDim.x + threadIdx.x) >> 5;
    int lane = threadIdx.x & 31;
    if (node >= n) return;

    int off = g_off[node];
    int deg = g_cnt[node];

    union { float2 f; __half2 h[2]; } q4;
    q4.f = *(const float2*)&g_qh[node * HID + lane * 4];
    float2 q0 = __half22float2(q4.h[0]), q1 = __half22float2(q4.h[1]);

    float a0 = 0.f, a1 = 0.f, a2 = 0.f, a3 = 0.f, esum = 0.f;

    for (int base = 0; base < deg; base += 32) {
        int rem = deg - base; if (rem > 32) rem = 32;
        int2 ad = make_int2(0, 0);
        if (lane < rem) ad = g_adj[off + base + lane];

        int j = 0;
        for (; j + 4 <= rem; j += 4) {
            int   c[4]; float gt[4];
#pragma unroll
            for (int u = 0; u < 4; u++) {
                c[u]  = __shfl_sync(0xFFFFFFFFu, ad.x, j + u);
                gt[u] = __int_as_float(__shfl_sync(0xFFFFFFFFu, ad.y, j + u));
            }
            union { float2 f; __half2 h[2]; } kk[4], vv[4];
#pragma unroll
            for (int u = 0; u < 4; u++) {
                kk[u].f = *(const float2*)&g_kh[c[u] * HID + lane * 4];
                vv[u].f = *(const float2*)&g_vh[c[u] * HID + lane * 4];
            }
            float p[4];
#pragma unroll
            for (int u = 0; u < 4; u++) {
                float2 k0 = __half22float2(kk[u].h[0]), k1 = __half22float2(kk[u].h[1]);
                p[u] = q0.x * k0.x + q0.y * k0.y + q1.x * k1.x + q1.y * k1.y;
            }
#pragma unroll
            for (int u = 0; u < 4; u++) p[u] += __shfl_xor_sync(0xFFFFFFFFu, p[u], 1);
#pragma unroll
            for (int u = 0; u < 4; u++) p[u] += __shfl_xor_sync(0xFFFFFFFFu, p[u], 2);
#pragma unroll
            for (int u = 0; u < 4; u++) p[u] += __shfl_xor_sync(0xFFFFFFFFu, p[u], 4);
#pragma unroll
            for (int u = 0; u < 4; u++) {
                float w = __expf(p[u] * gt[u]);
                float2 v0 = __half22float2(vv[u].h[0]), v1 = __half22float2(vv[u].h[1]);
                a0 += w * v0.x; a1 += w * v0.y; a2 += w * v1.x; a3 += w * v1.y;
                esum += w;
            }
        }
        for (; j < rem; j++) {
            int   c  = __shfl_sync(0xFFFFFFFFu, ad.x, j);
            float gt = __int_as_float(__shfl_sync(0xFFFFFFFFu, ad.y, j));
            union { float2 f; __half2 h[2]; } kk, vv;
            kk.f = *(const float2*)&g_kh[c * HID + lane * 4];
            vv.f = *(const float2*)&g_vh[c * HID + lane * 4];
            float2 k0 = __half22float2(kk.h[0]), k1 = __half22float2(kk.h[1]);
            float p = q0.x * k0.x + q0.y * k0.y + q1.x * k1.x + q1.y * k1.y;
            p += __shfl_xor_sync(0xFFFFFFFFu, p, 1);
            p += __shfl_xor_sync(0xFFFFFFFFu, p, 2);
            p += __shfl_xor_sync(0xFFFFFFFFu, p, 4);
            float w = __expf(p * gt);
            float2 v0 = __half22float2(vv.h[0]), v1 = __half22float2(vv.h[1]);
            a0 += w * v0.x; a1 += w * v0.y; a2 += w * v1.x; a3 += w * v1.y;
            esum += w;
        }
    }

    float inv = 1.f / (esum + 1e-16f);
    __half2* dst = (__half2*)&g_aggh[node * HID + lane * 4];
    dst[0] = __floats2half2_rn(a0 * inv, a1 * inv);
    dst[1] = __floats2half2_rn(a2 * inv, a3 * inv);
}

// ---------------- output projection: agg @ Wo^T + bo (tensor) ----------------
__global__ void __launch_bounds__(256, 2)
out_gemm(const float* __restrict__ Wo,
         const float* __restrict__ bo,
         float* __restrict__ out, int n) {
    __shared__ __align__(16) __half As[128][AK];
    __shared__ __align__(16) __half Bs[128][AK];

    int m0 = blockIdx.x * 128;
    int tid = threadIdx.x;
    int wid = tid >> 5, lane = tid & 31;
    int wm = (wid & 3) * 32;
    int wn = (wid >> 2) * 64;

    float acc[2][8][4];
#pragma unroll
    for (int i = 0; i < 2; i++)
#pragma unroll
        for (int j = 0; j < 8; j++)
#pragma unroll
            for (int t = 0; t < 4; t++) acc[i][j][t] = 0.f;

    for (int k0 = 0; k0 < HID; k0 += 64) {
        for (int idx = tid; idx < 128 * 16; idx += 256) {
            int r = idx >> 4;
            int k4 = (idx & 15) * 4;
            int m = m0 + r;
            uint2 val = make_uint2(0u, 0u);
            if (m < n) val = *(const uint2*)&g_aggh[m * HID + k0 + k4];
            *(uint2*)&As[r][k4] = val;
        }
        for (int idx = tid; idx < 128 * 16; idx += 256) {
            int c = idx >> 4;
            int k4 = (idx & 15) * 4;
            float4 wv = *(const float4*)&Wo[c * HID + k0 + k4];
            __half2* dst = (__half2*)&Bs[c][k4];
            dst[0] = __floats2half2_rn(wv.x, wv.y);
            dst[1] = __floats2half2_rn(wv.z, wv.w);
        }
        __syncthreads();

#pragma unroll
        for (int ks = 0; ks < 64; ks += 16) {
            unsigned af[2][4];
#pragma unroll
            for (int mf = 0; mf < 2; mf++) {
                unsigned a = smem_u32(&As[wm + mf * 16 + (lane & 15)][ks + (lane >> 4) * 8]);
                ldsm_x4(af[mf][0], af[mf][1], af[mf][2], af[mf][3], a);
            }
            unsigned bf[8][2];
#pragma unroll
            for (int ng = 0; ng < 4; ng++) {
                unsigned a = smem_u32(&Bs[wn + ng * 16 + (lane & 15)][ks + (lane >> 4) * 8]);
                unsigned r0, r1, r2, r3;
                ldsm_x4(r0, r1, r2, r3, a);
                bf[ng * 2][0] = r0; bf[ng * 2][1] = r2;
                bf[ng * 2 + 1][0] = r1; bf[ng * 2 + 1][1] = r3;
            }
#pragma unroll
            for (int mf = 0; mf < 2; mf++)
#pragma unroll
                for (int nf = 0; nf < 8; nf++)
                    mma16816(acc[mf][nf], af[mf], bf[nf]);
        }
        __syncthreads();
    }

#pragma unroll
    for (int mf = 0; mf < 2; mf++) {
        int r0 = m0 + wm + mf * 16 + (lane >> 2);
#pragma unroll
        for (int nf = 0; nf < 8; nf++) {
            int c = wn + nf * 8 + (lane & 3) * 2;
            float b0 = bo[c], b1 = bo[c + 1];
            if (r0 < n)
                *(float2*)&out[r0 * HID + c] =
                    make_float2(acc[mf][nf][0] + b0, acc[mf][nf][1] + b1);
            if (r0 + 8 < n)
                *(float2*)&out[(r0 + 8) * HID + c] =
                    make_float2(acc[mf][nf][2] + b0, acc[mf][nf][3] + b1);
        }
    }
}

// ---------------- launch ----------------------------------------------------
extern "C" void kernel_launch(void* const* d_in, const int* in_sizes, int n_in,
                              void* d_out, int out_size) {
    const float* h    = (const float*)d_in[0];
    const float* frac = (const float*)d_in[1];
    const float* dist = (const float*)d_in[2];
    const int*   ei   = (const int*)d_in[3];
    const float* We   = (const float*)d_in[4];
    const float* be   = (const float*)d_in[5];
    const float* Wq   = (const float*)d_in[6];
    const float* bq   = (const float*)d_in[7];
    const float* Wk   = (const float*)d_in[8];
    const float* bk   = (const float*)d_in[9];
    const float* Wv   = (const float*)d_in[10];
    const float* bv   = (const float*)d_in[11];
    const float* Wo   = (const float*)d_in[12];
    const float* bo   = (const float*)d_in[13];
    const float* Wg1  = (const float*)d_in[14];
    const float* bg1  = (const float*)d_in[15];
    const float* Wg2  = (const float*)d_in[16];
    const float* bg2  = (const float*)d_in[17];

    int n = in_sizes[0] / HID;
    int E = in_sizes[2];
    float* out = (float*)d_out;

    static int smem_set = 0;
    int qkv_smem = 128 * AKF * 2 + 128 * AK * 2 + 256 * 4 * 4;
    if (!smem_set) {
        cudaFuncSetAttribute(qkv_fused, cudaFuncAttributeMaxDynamicSharedMemorySize, qkv_smem);
        smem_set = 1;
    }

    zero_cnt<<<(n + 1023) / 1024, 1024>>>(n);
    qkv_fused<<<(n + 127) / 128, 256, qkv_smem>>>(h, frac, We, be, Wq, bq, Wk, bk, Wv, bv, n);
    hist_kernel<<<(E + 511) / 512, 512>>>(ei, E);

    int nch = (n + SCANB - 1) / SCANB;
    scan_phase1<<<nch, SCANB>>>(n);
    scan_phase2<<<1, 32>>>(nch);
    scan_phase3<<<nch, SCANB>>>(n);

    scatter_gate<<<(E + 7) / 8, 256>>>(ei, dist, Wg1, bg1, Wg2, bg2, E);
    pull_agg<<<(n + 7) / 8, 256>>>(n);
    out_gemm<<<(n + 127) / 128, 256>>>(Wo, bo, out, n);
}

// round 8
// speedup vs baseline: 1.1777x; 1.1777x over previous
#include <cuda_runtime.h>
#include <cuda_fp16.h>
#include <math.h>

#define HID   128
#define HEADS 4
#define HDIM  32
#define NMAX  50176
#define EMAX  800000

// ---------------- scratch ---------------------------------------------------
__device__ __half g_qh[NMAX * HID];
__device__ __half g_kh[NMAX * HID];
__device__ __half g_vh[NMAX * HID];
__device__ float  g_agg[NMAX * HID];     // unnormalized sum of w*v (fp32 atomics)
__device__ float  g_expsum[NMAX * HEADS];

// ---------------- mma helpers -----------------------------------------------
__device__ __forceinline__ unsigned smem_u32(const void* p) {
    return (unsigned)__cvta_generic_to_shared(p);
}
__device__ __forceinline__ void ldsm_x4(unsigned& r0, unsigned& r1,
                                        unsigned& r2, unsigned& r3, unsigned a) {
    asm volatile("ldmatrix.sync.aligned.m8n8.x4.shared.b16 {%0,%1,%2,%3},[%4];"
                 : "=r"(r0), "=r"(r1), "=r"(r2), "=r"(r3) : "r"(a));
}
__device__ __forceinline__ void mma16816(float* c, const unsigned* a, const unsigned* b) {
    asm volatile(
        "mma.sync.aligned.m16n8k16.row.col.f32.f16.f16.f32 "
        "{%0,%1,%2,%3},{%4,%5,%6,%7},{%8,%9},{%0,%1,%2,%3};"
        : "+f"(c[0]), "+f"(c[1]), "+f"(c[2]), "+f"(c[3])
        : "r"(a[0]), "r"(a[1]), "r"(a[2]), "r"(a[3]), "r"(b[0]), "r"(b[1]));
}

#define AKF 136   // full-K padded stride (halves)
#define AK  72    // chunk-K padded stride

// ---------------- zero scratch (vectorized) ----------------------------------
__global__ void zero_kernel(int n) {
    int i = blockIdx.x * blockDim.x + threadIdx.x;
    if (i < n * (HID / 4))
        *(float4*)&g_agg[i * 4] = make_float4(0.f, 0.f, 0.f, 0.f);
    if (i < n * HEADS) g_expsum[i] = 0.f;
}

// ---------------- fused QKV (single pass, tensor cores) ----------------------
// 128(M) x 128(N) tile, 8 warps x (32x64); loops Q,K,V reusing the A tile.
__global__ void __launch_bounds__(256, 2)
qkv_fused(const float* __restrict__ h,
          const float* __restrict__ frac,
          const float* __restrict__ We,
          const float* __restrict__ be,
          const float* __restrict__ Wq, const float* __restrict__ bq,
          const float* __restrict__ Wk, const float* __restrict__ bk,
          const float* __restrict__ Wv, const float* __restrict__ bv,
          int n) {
    extern __shared__ __align__(16) char smem_raw[];
    __half (*As)[AKF] = (__half(*)[AKF])smem_raw;
    __half (*Bs)[AK]  = (__half(*)[AK])(smem_raw + 128 * AKF * 2);
    float (*Fr)[4]  = (float(*)[4])(smem_raw + 128 * AKF * 2 + 128 * AK * 2);
    float (*Wes)[4] = Fr + 128;

    int m0 = blockIdx.x * 128;
    int tid = threadIdx.x;
    int wid = tid >> 5, lane = tid & 31;
    int wm = (wid & 3) * 32;
    int wn = (wid >> 2) * 64;

    if (tid < 128) {
        int kc = tid;
        Wes[kc][0] = We[kc * 3 + 0];
        Wes[kc][1] = We[kc * 3 + 1];
        Wes[kc][2] = We[kc * 3 + 2];
        Wes[kc][3] = be[kc];
        int m = m0 + tid;
        if (m < n) {
            Fr[tid][0] = frac[m * 3 + 0];
            Fr[tid][1] = frac[m * 3 + 1];
            Fr[tid][2] = frac[m * 3 + 2];
        } else {
            Fr[tid][0] = Fr[tid][1] = Fr[tid][2] = 0.f;
        }
    }
    __syncthreads();

    // build full-K A tile once (h read once)
    for (int idx = tid; idx < 128 * 32; idx += 256) {
        int r = idx >> 5;
        int k4 = (idx & 31) * 4;
        int m = m0 + r;
        float x[4] = {0.f, 0.f, 0.f, 0.f};
        if (m < n) {
            float4 hv = *(const float4*)&h[m * HID + k4];
            float f0 = Fr[r][0], f1 = Fr[r][1], f2 = Fr[r][2];
            x[0] = hv.x; x[1] = hv.y; x[2] = hv.z; x[3] = hv.w;
#pragma unroll
            for (int u = 0; u < 4; u++) {
                int kc = k4 + u;
                x[u] += f0 * Wes[kc][0] + f1 * Wes[kc][1] + f2 * Wes[kc][2] + Wes[kc][3];
            }
        }
        __half2* dst = (__half2*)&As[r][k4];
        dst[0] = __floats2half2_rn(x[0], x[1]);
        dst[1] = __floats2half2_rn(x[2], x[3]);
    }
    __syncthreads();

    const float* Ws[3] = {Wq, Wk, Wv};
    const float* bs[3] = {bq, bk, bv};
    __half* outs[3]; outs[0] = g_qh; outs[1] = g_kh; outs[2] = g_vh;

    for (int proj = 0; proj < 3; proj++) {
        const float* W = Ws[proj];
        float acc[2][8][4];
#pragma unroll
        for (int i = 0; i < 2; i++)
#pragma unroll
            for (int j = 0; j < 8; j++)
#pragma unroll
                for (int t = 0; t < 4; t++) acc[i][j][t] = 0.f;

        for (int k0 = 0; k0 < HID; k0 += 64) {
            for (int idx = tid; idx < 128 * 16; idx += 256) {
                int c = idx >> 4;
                int k4 = (idx & 15) * 4;
                float4 wv = *(const float4*)&W[c * HID + k0 + k4];
                __half2* dst = (__half2*)&Bs[c][k4];
                dst[0] = __floats2half2_rn(wv.x, wv.y);
                dst[1] = __floats2half2_rn(wv.z, wv.w);
            }
            __syncthreads();
#pragma unroll
            for (int ks = 0; ks < 64; ks += 16) {
                unsigned af[2][4];
#pragma unroll
                for (int mf = 0; mf < 2; mf++) {
                    unsigned a = smem_u32(&As[wm + mf * 16 + (lane & 15)][k0 + ks + (lane >> 4) * 8]);
                    ldsm_x4(af[mf][0], af[mf][1], af[mf][2], af[mf][3], a);
                }
                unsigned bf[8][2];
#pragma unroll
                for (int ng = 0; ng < 4; ng++) {
                    unsigned a = smem_u32(&Bs[wn + ng * 16 + (lane & 15)][ks + (lane >> 4) * 8]);
                    unsigned r0, r1, r2, r3;
                    ldsm_x4(r0, r1, r2, r3, a);
                    bf[ng * 2][0] = r0; bf[ng * 2][1] = r2;
                    bf[ng * 2 + 1][0] = r1; bf[ng * 2 + 1][1] = r3;
                }
#pragma unroll
                for (int mf = 0; mf < 2; mf++)
#pragma unroll
                    for (int nf = 0; nf < 8; nf++)
                        mma16816(acc[mf][nf], af[mf], bf[nf]);
            }
            __syncthreads();
        }

        const float* bias = bs[proj];
        __half* outbuf = outs[proj];
#pragma unroll
        for (int mf = 0; mf < 2; mf++) {
            int r0 = m0 + wm + mf * 16 + (lane >> 2);
#pragma unroll
            for (int nf = 0; nf < 8; nf++) {
                int c = wn + nf * 8 + (lane & 3) * 2;
                float b0 = bias[c], b1 = bias[c + 1];
                if (r0 < n)
                    *(__half2*)&outbuf[r0 * HID + c] =
                        __floats2half2_rn(acc[mf][nf][0] + b0, acc[mf][nf][1] + b1);
                if (r0 + 8 < n)
                    *(__half2*)&outbuf[(r0 + 8) * HID + c] =
                        __floats2half2_rn(acc[mf][nf][2] + b0, acc[mf][nf][3] + b1);
            }
        }
    }
}

// ---------------- fused per-edge: score + gate + exp + scatter w*v ----------
// one warp per edge; softmax max-shift skipped (scores O(1), ratio identical);
// normalization deferred to out_gemm.
__global__ void edge_fused(const int* __restrict__ ei,
                           const float* __restrict__ dist,
                           const float* __restrict__ Wg1, const float* __restrict__ bg1,
                           const float* __restrict__ Wg2, const float* __restrict__ bg2,
                           int E) {
    int warp = (blockIdx.x * blockDim.x + threadIdx.x) >> 5;
    int lane = threadIdx.x & 31;
    if (warp >= E) return;
    int row = __ldg(&ei[warp]);
    int col = __ldg(&ei[E + warp]);

    union { float2 f; __half2 h[2]; } q4, k4, v4;
    q4.f = *(const float2*)&g_qh[row * HID + lane * 4];
    k4.f = *(const float2*)&g_kh[col * HID + lane * 4];
    v4.f = *(const float2*)&g_vh[col * HID + lane * 4];

    float2 q0 = __half22float2(q4.h[0]), q1 = __half22float2(q4.h[1]);
    float2 k0 = __half22float2(k4.h[0]), k1 = __half22float2(k4.h[1]);
    float p = q0.x * k0.x + q0.y * k0.y + q1.x * k1.x + q1.y * k1.y;
    p += __shfl_xor_sync(0xFFFFFFFFu, p, 1);
    p += __shfl_xor_sync(0xFFFFFFFFu, p, 2);
    p += __shfl_xor_sync(0xFFFFFFFFu, p, 4);

    // gate MLP: 1 -> 32 (silu) -> 1 (sigmoid)
    float d = dist[warp];
    float t = fmaf(d, Wg1[lane], bg1[lane]);
    float hsi = t / (1.f + __expf(-t));
    float gp = hsi * Wg2[lane];
    gp += __shfl_xor_sync(0xFFFFFFFFu, gp, 16);
    gp += __shfl_xor_sync(0xFFFFFFFFu, gp, 8);
    gp += __shfl_xor_sync(0xFFFFFFFFu, gp, 4);
    gp += __shfl_xor_sync(0xFFFFFFFFu, gp, 2);
    gp += __shfl_xor_sync(0xFFFFFFFFu, gp, 1);
    float g = 1.f / (1.f + __expf(-(gp + bg2[0])));

    float w = __expf(p * 0.17677669529663687f * g);   // 1/sqrt(32)

    float2 v0 = __half22float2(v4.h[0]), v1 = __half22float2(v4.h[1]);
    float* dst = &g_agg[row * HID + lane * 4];
    asm volatile("red.global.add.v4.f32 [%0], {%1,%2,%3,%4};"
                 :: "l"(dst), "f"(w * v0.x), "f"(w * v0.y),
                    "f"(w * v1.x), "f"(w * v1.y));
    if ((lane & 7) == 0)
        atomicAdd(&g_expsum[row * HEADS + (lane >> 3)], w);
}

// ---------------- output projection: (agg/expsum) @ Wo^T + bo (tensor) ------
__global__ void __launch_bounds__(256, 2)
out_gemm(const float* __restrict__ Wo,
         const float* __restrict__ bo,
         float* __restrict__ out, int n) {
    __shared__ __align__(16) __half As[128][AK];
    __shared__ __align__(16) __half Bs[128][AK];
    __shared__ float Inv[128][4];

    int m0 = blockIdx.x * 128;
    int tid = threadIdx.x;
    int wid = tid >> 5, lane = tid & 31;
    int wm = (wid & 3) * 32;
    int wn = (wid >> 2) * 64;

    for (int t = tid; t < 128 * HEADS; t += 256) {
        int ml = t >> 2, hd = t & 3;
        int m = m0 + ml;
        Inv[ml][hd] = (m < n) ? 1.f / (g_expsum[m * HEADS + hd] + 1e-16f) : 0.f;
    }

    float acc[2][8][4];
#pragma unroll
    for (int i = 0; i < 2; i++)
#pragma unroll
        for (int j = 0; j < 8; j++)
#pragma unroll
            for (int t = 0; t < 4; t++) acc[i][j][t] = 0.f;

    __syncthreads();

    for (int k0 = 0; k0 < HID; k0 += 64) {
        for (int idx = tid; idx < 128 * 16; idx += 256) {
            int r = idx >> 4;
            int k4 = (idx & 15) * 4;
            int m = m0 + r;
            float x[4] = {0.f, 0.f, 0.f, 0.f};
            if (m < n) {
                float4 av = *(const float4*)&g_agg[m * HID + k0 + k4];
                float iv = Inv[r][(k0 + k4) >> 5];
                x[0] = av.x * iv; x[1] = av.y * iv; x[2] = av.z * iv; x[3] = av.w * iv;
            }
            __half2* dst = (__half2*)&As[r][k4];
            dst[0] = __floats2half2_rn(x[0], x[1]);
            dst[1] = __floats2half2_rn(x[2], x[3]);
        }
        for (int idx = tid; idx < 128 * 16; idx += 256) {
            int c = idx >> 4;
            int k4 = (idx & 15) * 4;
            float4 wv = *(const float4*)&Wo[c * HID + k0 + k4];
            __half2* dst = (__half2*)&Bs[c][k4];
            dst[0] = __floats2half2_rn(wv.x, wv.y);
            dst[1] = __floats2half2_rn(wv.z, wv.w);
        }
        __syncthreads();

#pragma unroll
        for (int ks = 0; ks < 64; ks += 16) {
            unsigned af[2][4];
#pragma unroll
            for (int mf = 0; mf < 2; mf++) {
                unsigned a = smem_u32(&As[wm + mf * 16 + (lane & 15)][ks + (lane >> 4) * 8]);
                ldsm_x4(af[mf][0], af[mf][1], af[mf][2], af[mf][3], a);
            }
            unsigned bf[8][2];
#pragma unroll
            for (int ng = 0; ng < 4; ng++) {
                unsigned a = smem_u32(&Bs[wn + ng * 16 + (lane & 15)][ks + (lane >> 4) * 8]);
                unsigned r0, r1, r2, r3;
                ldsm_x4(r0, r1, r2, r3, a);
                bf[ng * 2][0] = r0; bf[ng * 2][1] = r2;
                bf[ng * 2 + 1][0] = r1; bf[ng * 2 + 1][1] = r3;
            }
#pragma unroll
            for (int mf = 0; mf < 2; mf++)
#pragma unroll
                for (int nf = 0; nf < 8; nf++)
                    mma16816(acc[mf][nf], af[mf], bf[nf]);
        }
        __syncthreads();
    }

#pragma unroll
    for (int mf = 0; mf < 2; mf++) {
        int r0 = m0 + wm + mf * 16 + (lane >> 2);
#pragma unroll
        for (int nf = 0; nf < 8; nf++) {
            int c = wn + nf * 8 + (lane & 3) * 2;
            float b0 = bo[c], b1 = bo[c + 1];
            if (r0 < n)
                *(float2*)&out[r0 * HID + c] =
                    make_float2(acc[mf][nf][0] + b0, acc[mf][nf][1] + b1);
            if (r0 + 8 < n)
                *(float2*)&out[(r0 + 8) * HID + c] =
                    make_float2(acc[mf][nf][2] + b0, acc[mf][nf][3] + b1);
        }
    }
}

// ---------------- launch ----------------------------------------------------
extern "C" void kernel_launch(void* const* d_in, const int* in_sizes, int n_in,
                              void* d_out, int out_size) {
    const float* h    = (const float*)d_in[0];
    const float* frac = (const float*)d_in[1];
    const float* dist = (const float*)d_in[2];
    const int*   ei   = (const int*)d_in[3];
    const float* We   = (const float*)d_in[4];
    const float* be   = (const float*)d_in[5];
    const float* Wq   = (const float*)d_in[6];
    const float* bq   = (const float*)d_in[7];
    const float* Wk   = (const float*)d_in[8];
    const float* bk   = (const float*)d_in[9];
    const float* Wv   = (const float*)d_in[10];
    const float* bv   = (const float*)d_in[11];
    const float* Wo   = (const float*)d_in[12];
    const float* bo   = (const float*)d_in[13];
    const float* Wg1  = (const float*)d_in[14];
    const float* bg1  = (const float*)d_in[15];
    const float* Wg2  = (const float*)d_in[16];
    const float* bg2  = (const float*)d_in[17];

    int n = in_sizes[0] / HID;
    int E = in_sizes[2];
    float* out = (float*)d_out;

    static int smem_set = 0;
    int qkv_smem = 128 * AKF * 2 + 128 * AK * 2 + 256 * 4 * 4;
    if (!smem_set) {
        cudaFuncSetAttribute(qkv_fused, cudaFuncAttributeMaxDynamicSharedMemorySize, qkv_smem);
        smem_set = 1;
    }

    zero_kernel<<<(n * (HID / 4) + 1023) / 1024, 1024>>>(n);
    qkv_fused<<<(n + 127) / 128, 256, qkv_smem>>>(h, frac, We, be, Wq, bq, Wk, bk, Wv, bv, n);

    int eblocks = (E + 7) / 8;
    edge_fused<<<eblocks, 256>>>(ei, dist, Wg1, bg1, Wg2, bg2, E);

    out_gemm<<<(n + 127) / 128, 256>>>(Wo, bo, out, n);
}

// round 9
// speedup vs baseline: 1.3332x; 1.1320x over previous
#include <cuda_runtime.h>
#include <cuda_fp16.h>
#include <math.h>

#define HID   128
#define HEADS 4
#define HDIM  32
#define NMAX  50176
#define EMAX  800000

// ---------------- scratch ---------------------------------------------------
__device__ __half g_qh[NMAX * HID];
__device__ __half g_kh[NMAX * HID];
__device__ __half g_vh[NMAX * HID];
__device__ float  g_agg[NMAX * HID];     // unnormalized sum of w*v (fp32 atomics)
__device__ float  g_expsum[NMAX * HEADS];

// ---------------- mma helpers -----------------------------------------------
__device__ __forceinline__ unsigned smem_u32(const void* p) {
    return (unsigned)__cvta_generic_to_shared(p);
}
__device__ __forceinline__ void ldsm_x4(unsigned& r0, unsigned& r1,
                                        unsigned& r2, unsigned& r3, unsigned a) {
    asm volatile("ldmatrix.sync.aligned.m8n8.x4.shared.b16 {%0,%1,%2,%3},[%4];"
                 : "=r"(r0), "=r"(r1), "=r"(r2), "=r"(r3) : "r"(a));
}
__device__ __forceinline__ void mma16816(float* c, const unsigned* a, const unsigned* b) {
    asm volatile(
        "mma.sync.aligned.m16n8k16.row.col.f32.f16.f16.f32 "
        "{%0,%1,%2,%3},{%4,%5,%6,%7},{%8,%9},{%0,%1,%2,%3};"
        : "+f"(c[0]), "+f"(c[1]), "+f"(c[2]), "+f"(c[3])
        : "r"(a[0]), "r"(a[1]), "r"(a[2]), "r"(a[3]), "r"(b[0]), "r"(b[1]));
}

#define AK 72   // padded K stride (halves) for smem tiles

// ---------------- zero scratch (vectorized) ----------------------------------
__global__ void zero_kernel(int n) {
    int i = blockIdx.x * blockDim.x + threadIdx.x;
    if (i < n * (HID / 4))
        *(float4*)&g_agg[i * 4] = make_float4(0.f, 0.f, 0.f, 0.f);
    if (i < n * HEADS) g_expsum[i] = 0.f;
}

// ---------------- fused h_combined + QKV projections (tensor cores) ---------
// 128(M) x 128(N) per block, 8 warps x (32x64), K in 2 chunks of 64.
// blockIdx.y: 0=Q, 1=K, 2=V. Output fp16.  (R5 configuration — best measured)
__global__ void __launch_bounds__(256, 2)
qkv_gemm(const float* __restrict__ h,
         const float* __restrict__ frac,
         const float* __restrict__ We,
         const float* __restrict__ be,
         const float* __restrict__ Wq, const float* __restrict__ bq,
         const float* __restrict__ Wk, const float* __restrict__ bk,
         const float* __restrict__ Wv, const float* __restrict__ bv,
         int n) {
    __shared__ __align__(16) __half As[128][AK];
    __shared__ __align__(16) __half Bs[128][AK];
    __shared__ float Wes[128][4];   // We0,We1,We2,be
    __shared__ float Fr[128][4];    // frac x,y,z

    int m0 = blockIdx.x * 128;
    const float* W; const float* bias; __half* outbuf;
    if (blockIdx.y == 0)      { W = Wq; bias = bq; outbuf = g_qh; }
    else if (blockIdx.y == 1) { W = Wk; bias = bk; outbuf = g_kh; }
    else                      { W = Wv; bias = bv; outbuf = g_vh; }

    int tid = threadIdx.x;
    int wid = tid >> 5, lane = tid & 31;
    int wm = (wid & 3) * 32;
    int wn = (wid >> 2) * 64;

    if (tid < 128) {
        int kc = tid;
        Wes[kc][0] = We[kc * 3 + 0];
        Wes[kc][1] = We[kc * 3 + 1];
        Wes[kc][2] = We[kc * 3 + 2];
        Wes[kc][3] = be[kc];
        int m = m0 + tid;
        if (m < n) {
            Fr[tid][0] = frac[m * 3 + 0];
            Fr[tid][1] = frac[m * 3 + 1];
            Fr[tid][2] = frac[m * 3 + 2];
        } else {
            Fr[tid][0] = Fr[tid][1] = Fr[tid][2] = 0.f;
        }
    }

    float acc[2][8][4];
#pragma unroll
    for (int i = 0; i < 2; i++)
#pragma unroll
        for (int j = 0; j < 8; j++)
#pragma unroll
            for (int t = 0; t < 4; t++) acc[i][j][t] = 0.f;

    __syncthreads();

    for (int k0 = 0; k0 < HID; k0 += 64) {
        // A tile: h_combined[m0..+127][k0..+63] -> fp16
        for (int idx = tid; idx < 128 * 16; idx += 256) {
            int r = idx >> 4;
            int k4 = (idx & 15) * 4;
            int m = m0 + r;
            float x[4] = {0.f, 0.f, 0.f, 0.f};
            if (m < n) {
                float4 hv = *(const float4*)&h[m * HID + k0 + k4];
                float f0 = Fr[r][0], f1 = Fr[r][1], f2 = Fr[r][2];
                x[0] = hv.x; x[1] = hv.y; x[2] = hv.z; x[3] = hv.w;
#pragma unroll
                for (int u = 0; u < 4; u++) {
                    int kc = k0 + k4 + u;
                    x[u] += f0 * Wes[kc][0] + f1 * Wes[kc][1] + f2 * Wes[kc][2] + Wes[kc][3];
                }
            }
            __half2* dst = (__half2*)&As[r][k4];
            dst[0] = __floats2half2_rn(x[0], x[1]);
            dst[1] = __floats2half2_rn(x[2], x[3]);
        }
        // B tile: W[c][k0..+63] -> fp16
        for (int idx = tid; idx < 128 * 16; idx += 256) {
            int c = idx >> 4;
            int k4 = (idx & 15) * 4;
            float4 wv = *(const float4*)&W[c * HID + k0 + k4];
            __half2* dst = (__half2*)&Bs[c][k4];
            dst[0] = __floats2half2_rn(wv.x, wv.y);
            dst[1] = __floats2half2_rn(wv.z, wv.w);
        }
        __syncthreads();

#pragma unroll
        for (int ks = 0; ks < 64; ks += 16) {
            unsigned af[2][4];
#pragma unroll
            for (int mf = 0; mf < 2; mf++) {
                unsigned a = smem_u32(&As[wm + mf * 16 + (lane & 15)][ks + (lane >> 4) * 8]);
                ldsm_x4(af[mf][0], af[mf][1], af[mf][2], af[mf][3], a);
            }
            unsigned bf[8][2];
#pragma unroll
            for (int ng = 0; ng < 4; ng++) {
                unsigned a = smem_u32(&Bs[wn + ng * 16 + (lane & 15)][ks + (lane >> 4) * 8]);
                unsigned r0, r1, r2, r3;
                ldsm_x4(r0, r1, r2, r3, a);
                bf[ng * 2][0] = r0; bf[ng * 2][1] = r2;
                bf[ng * 2 + 1][0] = r1; bf[ng * 2 + 1][1] = r3;
            }
#pragma unroll
            for (int mf = 0; mf < 2; mf++)
#pragma unroll
                for (int nf = 0; nf < 8; nf++)
                    mma16816(acc[mf][nf], af[mf], bf[nf]);
        }
        __syncthreads();
    }

    // epilogue: add bias, store fp16
#pragma unroll
    for (int mf = 0; mf < 2; mf++) {
        int r0 = m0 + wm + mf * 16 + (lane >> 2);
#pragma unroll
        for (int nf = 0; nf < 8; nf++) {
            int c = wn + nf * 8 + (lane & 3) * 2;
            float b0 = bias[c], b1 = bias[c + 1];
            if (r0 < n)
                *(__half2*)&outbuf[r0 * HID + c] =
                    __floats2half2_rn(acc[mf][nf][0] + b0, acc[mf][nf][1] + b1);
            if (r0 + 8 < n)
                *(__half2*)&outbuf[(r0 + 8) * HID + c] =
                    __floats2half2_rn(acc[mf][nf][2] + b0, acc[mf][nf][3] + b1);
        }
    }
}

// ---------------- fused per-edge: TWO edges per warp (16 lanes each) --------
// half = lane>>4 selects edge; sub = lane&15 covers 8 halves (16B) of the row.
// head = sub>>2 (4 lanes per head). Gate MLP: 2 hidden units per lane.
__global__ void edge_fused2(const int* __restrict__ ei,
                            const float* __restrict__ dist,
                            const float* __restrict__ Wg1, const float* __restrict__ bg1,
                            const float* __restrict__ Wg2, const float* __restrict__ bg2,
                            int E) {
    int warp = (blockIdx.x * blockDim.x + threadIdx.x) >> 5;
    int lane = threadIdx.x & 31;
    int e0 = warp * 2;
    if (e0 >= E) return;
    int half = lane >> 4;
    int sub  = lane & 15;
    int edge = e0 + half;
    bool valid = edge < E;
    int esafe = valid ? edge : e0;

    int row = __ldg(&ei[esafe]);
    int col = __ldg(&ei[E + esafe]);

    // 16B (8 halves) per lane
    union { float4 f; __half2 h[4]; } q4, k4, v4;
    q4.f = *(const float4*)&g_qh[row * HID + sub * 8];
    k4.f = *(const float4*)&g_kh[col * HID + sub * 8];
    v4.f = *(const float4*)&g_vh[col * HID + sub * 8];

    float p = 0.f;
#pragma unroll
    for (int u = 0; u < 4; u++) {
        float2 qq = __half22float2(q4.h[u]);
        float2 kk = __half22float2(k4.h[u]);
        p += qq.x * kk.x + qq.y * kk.y;
    }
    // reduce over the 4 lanes of this head group
    p += __shfl_xor_sync(0xFFFFFFFFu, p, 1);
    p += __shfl_xor_sync(0xFFFFFFFFu, p, 2);

    // gate MLP: 1 -> 32 (silu) -> 1 (sigmoid); 2 hidden units per lane
    float d = __ldg(&dist[esafe]);
    int u0 = sub * 2;
    float t0 = fmaf(d, Wg1[u0], bg1[u0]);
    float t1 = fmaf(d, Wg1[u0 + 1], bg1[u0 + 1]);
    float gp = (t0 / (1.f + __expf(-t0))) * Wg2[u0]
             + (t1 / (1.f + __expf(-t1))) * Wg2[u0 + 1];
    // reduce over the 16 lanes of this half-warp
    gp += __shfl_xor_sync(0xFFFFFFFFu, gp, 8);
    gp += __shfl_xor_sync(0xFFFFFFFFu, gp, 4);
    gp += __shfl_xor_sync(0xFFFFFFFFu, gp, 2);
    gp += __shfl_xor_sync(0xFFFFFFFFu, gp, 1);
    float g = 1.f / (1.f + __expf(-(gp + bg2[0])));

    float w = __expf(p * 0.17677669529663687f * g);   // 1/sqrt(32)

    if (valid) {
        float* dst = &g_agg[row * HID + sub * 8];
        float2 v0 = __half22float2(v4.h[0]), v1 = __half22float2(v4.h[1]);
        float2 v2 = __half22float2(v4.h[2]), v3 = __half22float2(v4.h[3]);
        asm volatile("red.global.add.v4.f32 [%0], {%1,%2,%3,%4};"
                     :: "l"(dst), "f"(w * v0.x), "f"(w * v0.y),
                        "f"(w * v1.x), "f"(w * v1.y));
        asm volatile("red.global.add.v4.f32 [%0], {%1,%2,%3,%4};"
                     :: "l"(dst + 4), "f"(w * v2.x), "f"(w * v2.y),
                        "f"(w * v3.x), "f"(w * v3.y));
        if ((sub & 3) == 0)
            atomicAdd(&g_expsum[row * HEADS + (sub >> 2)], w);
    }
}

// ---------------- output projection: (agg/expsum) @ Wo^T + bo (tensor) ------
__global__ void __launch_bounds__(256, 2)
out_gemm(const float* __restrict__ Wo,
         const float* __restrict__ bo,
         float* __restrict__ out, int n) {
    __shared__ __align__(16) __half As[128][AK];
    __shared__ __align__(16) __half Bs[128][AK];
    __shared__ float Inv[128][4];

    int m0 = blockIdx.x * 128;
    int tid = threadIdx.x;
    int wid = tid >> 5, lane = tid & 31;
    int wm = (wid & 3) * 32;
    int wn = (wid >> 2) * 64;

    for (int t = tid; t < 128 * HEADS; t += 256) {
        int ml = t >> 2, hd = t & 3;
        int m = m0 + ml;
        Inv[ml][hd] = (m < n) ? 1.f / (g_expsum[m * HEADS + hd] + 1e-16f) : 0.f;
    }

    float acc[2][8][4];
#pragma unroll
    for (int i = 0; i < 2; i++)
#pragma unroll
        for (int j = 0; j < 8; j++)
#pragma unroll
            for (int t = 0; t < 4; t++) acc[i][j][t] = 0.f;

    __syncthreads();

    for (int k0 = 0; k0 < HID; k0 += 64) {
        for (int idx = tid; idx < 128 * 16; idx += 256) {
            int r = idx >> 4;
            int k4 = (idx & 15) * 4;
            int m = m0 + r;
            float x[4] = {0.f, 0.f, 0.f, 0.f};
            if (m < n) {
                float4 av = *(const float4*)&g_agg[m * HID + k0 + k4];
                float iv = Inv[r][(k0 + k4) >> 5];
                x[0] = av.x * iv; x[1] = av.y * iv; x[2] = av.z * iv; x[3] = av.w * iv;
            }
            __half2* dst = (__half2*)&As[r][k4];
            dst[0] = __floats2half2_rn(x[0], x[1]);
            dst[1] = __floats2half2_rn(x[2], x[3]);
        }
        for (int idx = tid; idx < 128 * 16; idx += 256) {
            int c = idx >> 4;
            int k4 = (idx & 15) * 4;
            float4 wv = *(const float4*)&Wo[c * HID + k0 + k4];
            __half2* dst = (__half2*)&Bs[c][k4];
            dst[0] = __floats2half2_rn(wv.x, wv.y);
            dst[1] = __floats2half2_rn(wv.z, wv.w);
        }
        __syncthreads();

#pragma unroll
        for (int ks = 0; ks < 64; ks += 16) {
            unsigned af[2][4];
#pragma unroll
            for (int mf = 0; mf < 2; mf++) {
                unsigned a = smem_u32(&As[wm + mf * 16 + (lane & 15)][ks + (lane >> 4) * 8]);
                ldsm_x4(af[mf][0], af[mf][1], af[mf][2], af[mf][3], a);
            }
            unsigned bf[8][2];
#pragma unroll
            for (int ng = 0; ng < 4; ng++) {
                unsigned a = smem_u32(&Bs[wn + ng * 16 + (lane & 15)][ks + (lane >> 4) * 8]);
                unsigned r0, r1, r2, r3;
                ldsm_x4(r0, r1, r2, r3, a);
                bf[ng * 2][0] = r0; bf[ng * 2][1] = r2;
                bf[ng * 2 + 1][0] = r1; bf[ng * 2 + 1][1] = r3;
            }
#pragma unroll
            for (int mf = 0; mf < 2; mf++)
#pragma unroll
                for (int nf = 0; nf < 8; nf++)
                    mma16816(acc[mf][nf], af[mf], bf[nf]);
        }
        __syncthreads();
    }

#pragma unroll
    for (int mf = 0; mf < 2; mf++) {
        int r0 = m0 + wm + mf * 16 + (lane >> 2);
#pragma unroll
        for (int nf = 0; nf < 8; nf++) {
            int c = wn + nf * 8 + (lane & 3) * 2;
            float b0 = bo[c], b1 = bo[c + 1];
            if (r0 < n)
                *(float2*)&out[r0 * HID + c] =
                    make_float2(acc[mf][nf][0] + b0, acc[mf][nf][1] + b1);
            if (r0 + 8 < n)
                *(float2*)&out[(r0 + 8) * HID + c] =
                    make_float2(acc[mf][nf][2] + b0, acc[mf][nf][3] + b1);
        }
    }
}

// ---------------- launch ----------------------------------------------------
extern "C" void kernel_launch(void* const* d_in, const int* in_sizes, int n_in,
                              void* d_out, int out_size) {
    const float* h    = (const float*)d_in[0];
    const float* frac = (const float*)d_in[1];
    const float* dist = (const float*)d_in[2];
    const int*   ei   = (const int*)d_in[3];
    const float* We   = (const float*)d_in[4];
    const float* be   = (const float*)d_in[5];
    const float* Wq   = (const float*)d_in[6];
    const float* bq   = (const float*)d_in[7];
    const float* Wk   = (const float*)d_in[8];
    const float* bk   = (const float*)d_in[9];
    const float* Wv   = (const float*)d_in[10];
    const float* bv   = (const float*)d_in[11];
    const float* Wo   = (const float*)d_in[12];
    const float* bo   = (const float*)d_in[13];
    const float* Wg1  = (const float*)d_in[14];
    const float* bg1  = (const float*)d_in[15];
    const float* Wg2  = (const float*)d_in[16];
    const float* bg2  = (const float*)d_in[17];

    int n = in_sizes[0] / HID;
    int E = in_sizes[2];
    float* out = (float*)d_out;

    zero_kernel<<<(n * (HID / 4) + 1023) / 1024, 1024>>>(n);

    dim3 gA((n + 127) / 128, 3);
    qkv_gemm<<<gA, 256>>>(h, frac, We, be, Wq, bq, Wk, bk, Wv, bv, n);

    int warps = (E + 1) / 2;
    edge_fused2<<<(warps + 7) / 8, 256>>>(ei, dist, Wg1, bg1, Wg2, bg2, E);

    out_gemm<<<(n + 127) / 128, 256>>>(Wo, bo, out, n);
}